// round 10
// baseline (speedup 1.0000x reference)
#include <cuda_runtime.h>

// Problem constants (fixed by the reference):
//   encoder_outputs : [B, L, D] f32   = d_in[0]
//   durations       : [B, L]    i32   = d_in[1]
//   frames_positions: [B, T, P] f32   = d_in[2]
//   input_lengths   : [B]       i32   = d_in[3]  (UNUSED by reference)
//   output          : [B, T, D+P] f32
#define BB 16
#define LL 512
#define DD 512
#define TT 4096
#define PP 4

#define DV (DD / 4)          // 128 float4 per encoder row
#define ROW_V (DV + 1)       // 129 float4 per output row (516 floats, 2064 B)
#define RPG 8                // rows per 128-lane group (ILP batch)
#define ROWS_PB 32           // rows per block (4 groups * RPG)
#define BLKS_PER_B (TT / ROWS_PB)   // 128 blocks per batch

// ---------------------------------------------------------------------------
// Single fused kernel (round-9 structure).
// Round-10 change: DEFAULT-policy stores instead of __stcs. The harness
// replays the graph on the same output buffer; 135 MB of output vs 126 MB of
// L2 means default writes become L2 write-hits on dirty-resident lines in
// steady state, cutting DRAM write-back per replay. __stcs (evict-first) was
// forcing the full write stream to DRAM every iteration.
// ---------------------------------------------------------------------------
__global__ __launch_bounds__(512) void durian_fused_kernel(
    const int*    __restrict__ dur,   // [B, L]
    const float4* __restrict__ enc,   // [B*L, 128] float4
    const float4* __restrict__ fp,    // [B*T] float4
    float4*       __restrict__ out)   // [B*T, 129] float4
{
    __shared__ int s_wsum[16];
    __shared__ int s_idx[ROWS_PB];

    const int tid   = threadIdx.x;
    const int b     = blockIdx.x >> 7;            // / BLKS_PER_B
    const int blk   = blockIdx.x & (BLKS_PER_B - 1);
    const int t0    = blk * ROWS_PB;              // first frame of this block
    const int row0g = b * TT + t0;                // first global output row

    // ---- Phase A: per-batch inclusive cumsum of durations (L=512) --------
    const int lane = tid & 31;
    const int wid  = tid >> 5;                    // 16 warps
    const int d    = dur[b * LL + tid];           // one duration per thread
    int x = d;
    #pragma unroll
    for (int o = 1; o < 32; o <<= 1) {
        int y = __shfl_up_sync(0xffffffffu, x, o);
        if (lane >= o) x += y;
    }
    if (lane == 31) s_wsum[wid] = x;
    if (tid < ROWS_PB) s_idx[tid] = -1;           // init window map
    __syncthreads();
    if (wid == 0) {
        int w = (lane < 16) ? s_wsum[lane] : 0;
        #pragma unroll
        for (int o = 1; o < 16; o <<= 1) {
            int y = __shfl_up_sync(0xffffffffu, w, o);
            if (lane >= o) w += y;
        }
        if (lane < 16) s_wsum[lane] = w;          // inclusive warp prefix
    }
    __syncthreads();

    // Token tid covers frames [end - d, end) with end = inclusive cumsum.
    const int prefix = (wid == 0) ? 0 : s_wsum[wid - 1];
    const int end    = prefix + x;
    const int start  = end - d;

    // Scatter into this block's 32-frame window (disjoint ranges, no races)
    int lo = start > t0 ? start : t0;
    int hi = end < t0 + ROWS_PB ? end : t0 + ROWS_PB;
    for (int t = lo; t < hi; t++)
        s_idx[t - t0] = tid;
    __syncthreads();

    // ---- Phase B: expansion + concat ------------------------------------
    const int grp   = tid >> 7;                   // 0..3 group within block
    const int flane = tid & 127;                  // float4 column within row
    const int lrow0 = grp * RPG;                  // local first row of group
    const int rowg  = row0g + lrow0;              // first global row of group

    int idx[RPG];
    #pragma unroll
    for (int r = 0; r < RPG; r++)
        idx[r] = s_idx[lrow0 + r];                // LDS broadcast

    // Positions tail value (independent load, overlaps the gathers)
    float4 tail;
    if (flane < RPG)
        tail = fp[rowg + flane];

    const float4* encb = enc + (size_t)b * LL * DV;
    float4 v[RPG];
    #pragma unroll
    for (int r = 0; r < RPG; r++) {
        if (idx[r] >= 0)
            v[r] = encb[(size_t)idx[r] * DV + flane];
        else
            v[r] = make_float4(0.f, 0.f, 0.f, 0.f);
    }

    // Default-policy stores: let L2 retain the output working set across
    // graph replays (write hits on dirty-resident lines -> no DRAM trip).
    #pragma unroll
    for (int r = 0; r < RPG; r++)
        out[(size_t)(rowg + r) * ROW_V + flane] = v[r];

    // Positions tail: lanes 0..7 of each group handle one row each
    if (flane < RPG)
        out[(size_t)(rowg + flane) * ROW_V + DV] = tail;
}

extern "C" void kernel_launch(void* const* d_in, const int* in_sizes, int n_in,
                              void* d_out, int out_size) {
    const float* enc = (const float*)d_in[0];
    const int*   dur = (const int*)  d_in[1];
    const float* fp  = (const float*)d_in[2];
    // d_in[3] = input_lengths: unused by the reference.
    (void)in_sizes; (void)n_in; (void)out_size;

    durian_fused_kernel<<<BB * BLKS_PER_B, 512>>>(
        dur,
        (const float4*)enc,
        (const float4*)fp,
        (float4*)d_out);
}

// round 11
// speedup vs baseline: 1.1909x; 1.1909x over previous
#include <cuda_runtime.h>

// Problem constants (fixed by the reference):
//   encoder_outputs : [B, L, D] f32   = d_in[0]
//   durations       : [B, L]    i32   = d_in[1]
//   frames_positions: [B, T, P] f32   = d_in[2]
//   input_lengths   : [B]       i32   = d_in[3]  (UNUSED by reference)
//   output          : [B, T, D+P] f32
#define BB 16
#define LL 512
#define DD 512
#define TT 4096
#define PP 4

#define DV (DD / 4)          // 128 float4 per encoder row
#define ROW_V (DV + 1)       // 129 float4 per output row (516 floats, 2064 B)
#define ROWS_PB 32           // rows (frames) per block
#define BLKS_PER_B (TT / ROWS_PB)       // 128 blocks per batch
#define BLK_F4 (ROWS_PB * ROW_V)        // 4128 float4 per block (66048 B, 128B-aligned)

// ---------------------------------------------------------------------------
// Single fused kernel, round-11:
//  - __stcs streaming stores RESTORED (round-10 showed default policy churns
//    L2 across graph replays: +5us wall time at identical one-shot time).
//  - Output emitted as a LINEAR ALIGNED float4 stream over the block's
//    contiguous 66048-byte region (base = row0g*2064 is 128B-aligned since
//    row0g % 32 == 0). Row-oriented stores had half the warps misaligned to
//    128B lines (2064B row stride), costing ~25% extra store wavefronts.
//    Each thread maps flat index i -> (row=i/129, col=i%129) and gathers
//    enc[s_idx[row]][col], or the positions tail at col==128.
// ---------------------------------------------------------------------------
__global__ __launch_bounds__(512) void durian_fused_kernel(
    const int*    __restrict__ dur,   // [B, L]
    const float4* __restrict__ enc,   // [B*L, 128] float4
    const float4* __restrict__ fp,    // [B*T] float4
    float4*       __restrict__ out)   // [B*T, 129] float4
{
    __shared__ int s_wsum[16];
    __shared__ int s_idx[ROWS_PB];

    const int tid   = threadIdx.x;
    const int b     = blockIdx.x >> 7;            // / BLKS_PER_B
    const int blk   = blockIdx.x & (BLKS_PER_B - 1);
    const int t0    = blk * ROWS_PB;              // first frame of this block
    const int row0g = b * TT + t0;                // first global output row

    // ---- Phase A: per-batch inclusive cumsum of durations (L=512) --------
    const int lane = tid & 31;
    const int wid  = tid >> 5;                    // 16 warps
    const int d    = dur[b * LL + tid];           // one duration per thread
    int x = d;
    #pragma unroll
    for (int o = 1; o < 32; o <<= 1) {
        int y = __shfl_up_sync(0xffffffffu, x, o);
        if (lane >= o) x += y;
    }
    if (lane == 31) s_wsum[wid] = x;
    if (tid < ROWS_PB) s_idx[tid] = -1;           // init window map
    __syncthreads();
    if (wid == 0) {
        int w = (lane < 16) ? s_wsum[lane] : 0;
        #pragma unroll
        for (int o = 1; o < 16; o <<= 1) {
            int y = __shfl_up_sync(0xffffffffu, w, o);
            if (lane >= o) w += y;
        }
        if (lane < 16) s_wsum[lane] = w;          // inclusive warp prefix
    }
    __syncthreads();

    // Token tid covers frames [end - d, end); end = inclusive cumsum.
    const int prefix = (wid == 0) ? 0 : s_wsum[wid - 1];
    const int end    = prefix + x;
    const int start  = end - d;

    // Scatter into this block's 32-frame window (disjoint ranges, no races)
    int lo = start > t0 ? start : t0;
    int hi = end < t0 + ROWS_PB ? end : t0 + ROWS_PB;
    for (int t = lo; t < hi; t++)
        s_idx[t - t0] = tid;
    __syncthreads();

    // ---- Phase B: linear aligned streaming of the block's output region --
    const float4* encb = enc + (size_t)b * LL * DV;
    float4* oblk = out + (size_t)row0g * ROW_V;   // 128B-aligned block base

    // 4128 f4 = 8 * 512 + 32: 8 full sweeps + a 32-thread tail.
    #pragma unroll
    for (int it = 0; it < 8; it++) {
        const int i   = tid + it * 512;           // flat f4 index in block
        const int row = i / ROW_V;                // local frame 0..31
        const int col = i - row * ROW_V;          // 0..128
        const int idx = s_idx[row];

        float4 v;
        if (col == DV) {
            v = fp[row0g + row];                  // positions tail
        } else if (idx >= 0) {
            v = encb[(size_t)idx * DV + col];
        } else {
            v = make_float4(0.f, 0.f, 0.f, 0.f);
        }
        __stcs(&oblk[i], v);
    }
    if (tid < BLK_F4 - 8 * 512) {                 // tail: i in [4096, 4128)
        const int i   = tid + 8 * 512;
        const int row = i / ROW_V;
        const int col = i - row * ROW_V;
        const int idx = s_idx[row];

        float4 v;
        if (col == DV) {
            v = fp[row0g + row];
        } else if (idx >= 0) {
            v = encb[(size_t)idx * DV + col];
        } else {
            v = make_float4(0.f, 0.f, 0.f, 0.f);
        }
        __stcs(&oblk[i], v);
    }
}

extern "C" void kernel_launch(void* const* d_in, const int* in_sizes, int n_in,
                              void* d_out, int out_size) {
    const float* enc = (const float*)d_in[0];
    const int*   dur = (const int*)  d_in[1];
    const float* fp  = (const float*)d_in[2];
    // d_in[3] = input_lengths: unused by the reference.
    (void)in_sizes; (void)n_in; (void)out_size;

    durian_fused_kernel<<<BB * BLKS_PER_B, 512>>>(
        dur,
        (const float4*)enc,
        (const float4*)fp,
        (float4*)d_out);
}

// round 12
// speedup vs baseline: 1.2031x; 1.0102x over previous
#include <cuda_runtime.h>

// Problem constants (fixed by the reference):
//   encoder_outputs : [B, L, D] f32   = d_in[0]
//   durations       : [B, L]    i32   = d_in[1]
//   frames_positions: [B, T, P] f32   = d_in[2]
//   input_lengths   : [B]       i32   = d_in[3]  (UNUSED by reference)
//   output          : [B, T, D+P] f32
#define BB 16
#define LL 512
#define DD 512
#define TT 4096
#define PP 4

#define DV (DD / 4)          // 128 float4 per encoder row
#define ROW_V (DV + 1)       // 129 float4 per output row (516 floats, 2064 B)
#define ROWS_PB 32           // rows (frames) per block
#define BLKS_PER_B (TT / ROWS_PB)       // 128 blocks per batch
#define BLK_F4 (ROWS_PB * ROW_V)        // 4128 float4 per block (66048 B, 128B-aligned)

// ---------------------------------------------------------------------------
// Single fused kernel, round-11:
//  - __stcs streaming stores RESTORED (round-10 showed default policy churns
//    L2 across graph replays: +5us wall time at identical one-shot time).
//  - Output emitted as a LINEAR ALIGNED float4 stream over the block's
//    contiguous 66048-byte region (base = row0g*2064 is 128B-aligned since
//    row0g % 32 == 0). Row-oriented stores had half the warps misaligned to
//    128B lines (2064B row stride), costing ~25% extra store wavefronts.
//    Each thread maps flat index i -> (row=i/129, col=i%129) and gathers
//    enc[s_idx[row]][col], or the positions tail at col==128.
// ---------------------------------------------------------------------------
__global__ __launch_bounds__(512) void durian_fused_kernel(
    const int*    __restrict__ dur,   // [B, L]
    const float4* __restrict__ enc,   // [B*L, 128] float4
    const float4* __restrict__ fp,    // [B*T] float4
    float4*       __restrict__ out)   // [B*T, 129] float4
{
    __shared__ int s_wsum[16];
    __shared__ int s_idx[ROWS_PB];

    const int tid   = threadIdx.x;
    const int b     = blockIdx.x >> 7;            // / BLKS_PER_B
    const int blk   = blockIdx.x & (BLKS_PER_B - 1);
    const int t0    = blk * ROWS_PB;              // first frame of this block
    const int row0g = b * TT + t0;                // first global output row

    // ---- Phase A: per-batch inclusive cumsum of durations (L=512) --------
    const int lane = tid & 31;
    const int wid  = tid >> 5;                    // 16 warps
    const int d    = dur[b * LL + tid];           // one duration per thread
    int x = d;
    #pragma unroll
    for (int o = 1; o < 32; o <<= 1) {
        int y = __shfl_up_sync(0xffffffffu, x, o);
        if (lane >= o) x += y;
    }
    if (lane == 31) s_wsum[wid] = x;
    if (tid < ROWS_PB) s_idx[tid] = -1;           // init window map
    __syncthreads();
    if (wid == 0) {
        int w = (lane < 16) ? s_wsum[lane] : 0;
        #pragma unroll
        for (int o = 1; o < 16; o <<= 1) {
            int y = __shfl_up_sync(0xffffffffu, w, o);
            if (lane >= o) w += y;
        }
        if (lane < 16) s_wsum[lane] = w;          // inclusive warp prefix
    }
    __syncthreads();

    // Token tid covers frames [end - d, end); end = inclusive cumsum.
    const int prefix = (wid == 0) ? 0 : s_wsum[wid - 1];
    const int end    = prefix + x;
    const int start  = end - d;

    // Scatter into this block's 32-frame window (disjoint ranges, no races)
    int lo = start > t0 ? start : t0;
    int hi = end < t0 + ROWS_PB ? end : t0 + ROWS_PB;
    for (int t = lo; t < hi; t++)
        s_idx[t - t0] = tid;
    __syncthreads();

    // ---- Phase B: linear aligned streaming of the block's output region --
    const float4* encb = enc + (size_t)b * LL * DV;
    float4* oblk = out + (size_t)row0g * ROW_V;   // 128B-aligned block base

    // 4128 f4 = 8 * 512 + 32: 8 full sweeps + a 32-thread tail.
    #pragma unroll
    for (int it = 0; it < 8; it++) {
        const int i   = tid + it * 512;           // flat f4 index in block
        const int row = i / ROW_V;                // local frame 0..31
        const int col = i - row * ROW_V;          // 0..128
        const int idx = s_idx[row];

        float4 v;
        if (col == DV) {
            v = fp[row0g + row];                  // positions tail
        } else if (idx >= 0) {
            v = encb[(size_t)idx * DV + col];
        } else {
            v = make_float4(0.f, 0.f, 0.f, 0.f);
        }
        __stcs(&oblk[i], v);
    }
    if (tid < BLK_F4 - 8 * 512) {                 // tail: i in [4096, 4128)
        const int i   = tid + 8 * 512;
        const int row = i / ROW_V;
        const int col = i - row * ROW_V;
        const int idx = s_idx[row];

        float4 v;
        if (col == DV) {
            v = fp[row0g + row];
        } else if (idx >= 0) {
            v = encb[(size_t)idx * DV + col];
        } else {
            v = make_float4(0.f, 0.f, 0.f, 0.f);
        }
        __stcs(&oblk[i], v);
    }
}

extern "C" void kernel_launch(void* const* d_in, const int* in_sizes, int n_in,
                              void* d_out, int out_size) {
    const float* enc = (const float*)d_in[0];
    const int*   dur = (const int*)  d_in[1];
    const float* fp  = (const float*)d_in[2];
    // d_in[3] = input_lengths: unused by the reference.
    (void)in_sizes; (void)n_in; (void)out_size;

    durian_fused_kernel<<<BB * BLKS_PER_B, 512>>>(
        dur,
        (const float4*)enc,
        (const float4*)fp,
        (float4*)d_out);
}